// round 15
// baseline (speedup 1.0000x reference)
#include <cuda_runtime.h>
#include <cuda_fp16.h>
#include <cstdint>

// ---------------------------------------------------------------------------
// DoseEncoder — warp-autonomous j-packed f32x2, 2-t weight amortization.
//
//  * 3-kernel pipeline: dtlast (binary search) -> main -> combine.
//  * main: grid (T/64, 4). Block = 128 thr; warp w owns 16 t over the
//    block's 64 doses (2/thread, f32x2 lanes = hidden-j pairs).
//    Processes 2 t's per iteration: each smem weight load feeds 8 FFMA2
//    (2 doses x 2 t) -> LDS wavefronts per warp-t nearly halve.
//  * Prescale-by-0.5 on layers 1-3: silu(x) = y + y*tanh(y), y = x/2.
//  * h2 (layer-2 output) kept in registers as fp16x2 (64 u32 for 2t x 2d
//    x 32j) so layer-3 accumulators fit; layer 3 in jp-quarter passes.
//  * NO barriers in the main loop.
// ---------------------------------------------------------------------------

#define TPB   128
#define T_MAX 32768

typedef unsigned long long ull;

__device__ float g_dtlast[T_MAX];
__device__ float g_part[4 * T_MAX];

// dynamic smem layout (byte offsets)
#define OFF_W2   0        // ull[32][16]  0.5*W2 j-packed, 128B rows  (4 KB)
#define OFF_W3   4096     // ull[32][16]                              (4 KB)
#define OFF_V    8192     // ull[32][32]  [i][lane] {0.5*VA_i, 0.5*VB_i} (8 KB)
#define OFF_W1TD 16384    // ull[32]  dup{0.5*W1t_i}
#define OFF_W1DD 16640    // ull[32]  dup{0.5*W1dl_i}
#define OFF_B2   16896    // ull[16]  {0.5*b2} j-packed
#define OFF_B3   17024
#define OFF_W4   17152    // ull[16]  {w4} j-packed (UNscaled)
#define SMEM_DYN 17280

// ---- packed f32x2 helpers --------------------------------------------------
__device__ __forceinline__ ull packf2(float a, float b) {
    ull r; asm("mov.b64 %0, {%1, %2};" : "=l"(r) : "f"(a), "f"(b)); return r;
}
__device__ __forceinline__ void unpackf2(ull x, float& a, float& b) {
    asm("mov.b64 {%0, %1}, %2;" : "=f"(a), "=f"(b) : "l"(x));
}
__device__ __forceinline__ ull dupf(float a) {
    ull r; asm("mov.b64 %0, {%1, %1};" : "=l"(r) : "f"(a)); return r;
}
__device__ __forceinline__ ull fma2u(ull a, ull b, ull c) {
    ull r; asm("fma.rn.f32x2 %0, %1, %2, %3;" : "=l"(r) : "l"(a), "l"(b), "l"(c));
    return r;
}
__device__ __forceinline__ float ex2f(float x) {
    float r; asm("ex2.approx.f32 %0, %1;" : "=f"(r) : "f"(x)); return r;
}
__device__ __forceinline__ float tanhf_(float x) {
    float r; asm("tanh.approx.f32 %0, %1;" : "=f"(r) : "f"(x)); return r;
}
// input y = x/2 (prescaled). silu(x) = y + y*tanh(y), both lanes.
__device__ __forceinline__ ull silup(ull y) {
    float y0, y1; unpackf2(y, y0, y1);
    float t0 = tanhf_(y0), t1 = tanhf_(y1);
    return fma2u(y, packf2(t0, t1), y);
}
// f32x2 (ull) -> f16x2 (u32): lo -> .x, hi -> .y
__device__ __forceinline__ uint32_t f2_to_h2(ull v) {
    float lo, hi; unpackf2(v, lo, hi);
    __half2 h = __floats2half2_rn(lo, hi);
    return *reinterpret_cast<uint32_t*>(&h);
}
// f16x2 (u32) -> float2 {x=even j, y=odd j}
__device__ __forceinline__ float2 h2_to_f2(uint32_t u) {
    __half2 h = *reinterpret_cast<__half2*>(&u);
    return __half22float2(h);
}

// ---------------------------------------------------------------------------
// Kernel 1: dt_last via binary search (doses sorted ascending).
// ---------------------------------------------------------------------------
__global__ void dtlast_kernel(const float* __restrict__ t_abs,
                              const float* __restrict__ dose_t,
                              const float* __restrict__ span_p,
                              int T, int D) {
    int i = blockIdx.x * blockDim.x + threadIdx.x;
    if (i >= T) return;
    float ta = t_abs[i];
    float inv_span = 1.0f / span_p[0];
    int pos = 0;
#pragma unroll
    for (int s = 256; s > 0; s >>= 1) {
        int np = pos + s;
        if (np <= D && dose_t[np - 1] <= ta) pos = np;
    }
    g_dtlast[i] = (pos > 0) ? (ta - dose_t[pos - 1]) * inv_span
                            : __int_as_float(0x7f800000);
}

// ---------------------------------------------------------------------------
// Kernel 2: main. grid = (T/64, 4) x 128 threads.
// ---------------------------------------------------------------------------
__global__ void __launch_bounds__(TPB, 3)
dose_encoder_kernel(const float* __restrict__ t_abs,
                    const float* __restrict__ dose_t,
                    const float* __restrict__ amts,
                    const float* __restrict__ ss,
                    const float* __restrict__ ii,
                    const float* __restrict__ span_p,
                    const float* __restrict__ logsig,
                    const float* __restrict__ W1,
                    const float* __restrict__ b1,
                    const float* __restrict__ W2,
                    const float* __restrict__ b2,
                    const float* __restrict__ W3,
                    const float* __restrict__ b3,
                    const float* __restrict__ W4,
                    const float* __restrict__ b4,
                    int T) {
    extern __shared__ char sm[];
    ull* W2p  = (ull*)(sm + OFF_W2);
    ull* W3p  = (ull*)(sm + OFF_W3);
    ull* Vab  = (ull*)(sm + OFF_V);
    ull* W1Td = (ull*)(sm + OFF_W1TD);
    ull* W1Dd = (ull*)(sm + OFF_W1DD);
    ull* B2p  = (ull*)(sm + OFF_B2);
    ull* B3p  = (ull*)(sm + OFF_B3);
    ull* W4p  = (ull*)(sm + OFF_W4);

    const int tid  = threadIdx.x;
    const int lane = tid & 31;
    const int warp = tid >> 5;
    const int q    = blockIdx.y;
    const int dq0  = q * 64;

    const float span     = span_p[0];
    const float inv_span = 1.0f / span;
    const float sigma    = expf(logsig[0]);
    const float wc_l2    = -0.5f / (sigma * sigma) * 1.4426950408889634f;
    const float b4v      = b4[0];

    // ---- prolog: prescaled weight staging ----
    for (int idx = tid; idx < 512; idx += TPB) {
        int i = idx >> 4, jp = idx & 15;
        W2p[idx] = packf2(0.5f * W2[i * 32 + 2 * jp], 0.5f * W2[i * 32 + 2 * jp + 1]);
        W3p[idx] = packf2(0.5f * W3[i * 32 + 2 * jp], 0.5f * W3[i * 32 + 2 * jp + 1]);
    }
    if (tid < 32) {
        W1Td[tid] = dupf(0.5f * W1[tid]);
        W1Dd[tid] = dupf(0.5f * W1[64 + tid]);
    }
    if (tid < 16) {
        B2p[tid] = packf2(0.5f * b2[2 * tid], 0.5f * b2[2 * tid + 1]);
        B3p[tid] = packf2(0.5f * b3[2 * tid], 0.5f * b3[2 * tid + 1]);
        W4p[tid] = packf2(W4[2 * tid], W4[2 * tid + 1]);
    }

    // ---- V vectors (prescaled, incl. 0.5*b1): warp w fills i-rows 8w..8w+7 ----
    {
        int da = dq0 + 2 * lane, db = da + 1;
        float dnAx = dose_t[da] * inv_span, dnBx = dose_t[db] * inv_span;
        float laA = log1pf(amts[da]),       laB = log1pf(amts[db]);
        float spe = 1.0f / (span + 1e-6f);
        float ssA = ss[da] * spe, ssB = ss[db] * spe;
        float iiA = ii[da] * spe, iiB = ii[db] * spe;
        for (int i = warp * 8; i < warp * 8 + 8; i++) {
            float wdt = W1[i], wla = W1[32 + i];
            float wss = W1[96 + i], wii = W1[128 + i];
            float bb  = b1[i];
            float vA = fmaf(-dnAx, wdt, fmaf(laA, wla, fmaf(ssA, wss, fmaf(iiA, wii, bb))));
            float vB = fmaf(-dnBx, wdt, fmaf(laB, wla, fmaf(ssB, wss, fmaf(iiB, wii, bb))));
            Vab[i * 32 + lane] = packf2(0.5f * vA, 0.5f * vB);
        }
    }
    __syncthreads();   // the ONLY block barrier

    const int dA = dq0 + 2 * lane, dB = dA + 1;
    const float dnA = dose_t[dA] * inv_span;
    const float dnB = dose_t[dB] * inv_span;

    const unsigned smb    = (unsigned)__cvta_generic_to_shared(sm);
    const unsigned w2base = smb + OFF_W2;
    const unsigned w3base = smb + OFF_W3;

    const int tbase = blockIdx.x * 64 + warp * 16;
    float* __restrict__ part_out = g_part + q * T_MAX;

#pragma unroll 1
    for (int g = 0; g < 8; g++) {
        int tt0 = tbase + 2 * g;
        if (tt0 >= T) break;
        int tt1  = tt0 + 1;
        int tt1c = (tt1 < T) ? tt1 : tt0;

        float tn0 = t_abs[tt0]  * inv_span;
        float tn1 = t_abs[tt1c] * inv_span;
        float dl0 = g_dtlast[tt0];
        float dl1 = g_dtlast[tt1c];
        ull tn20 = dupf(tn0), dl20 = dupf(dl0);
        ull tn21 = dupf(tn1), dl21 = dupf(dl1);

        // ==== layer 2 full-width for 2 t's, layer 1 fused ====
        ull accA0[16], accB0[16], accA1[16], accB1[16];
#pragma unroll
        for (int jp = 0; jp < 16; jp++) {
            ull bb = B2p[jp];
            accA0[jp] = bb; accB0[jp] = bb; accA1[jp] = bb; accB1[jp] = bb;
        }

#pragma unroll 4
        for (int i = 0; i < 32; i++) {
            ull v  = Vab[i * 32 + lane];
            ull td = W1Td[i], dd = W1Dd[i];
            ull h0 = silup(fma2u(tn20, td, fma2u(dl20, dd, v)));
            ull h1 = silup(fma2u(tn21, td, fma2u(dl21, dd, v)));
            float hA0, hB0, hA1, hB1;
            unpackf2(h0, hA0, hB0);
            unpackf2(h1, hA1, hB1);
            ull dA0 = dupf(hA0), dB0 = dupf(hB0);
            ull dA1 = dupf(hA1), dB1 = dupf(hB1);
            unsigned rb = w2base + (unsigned)i * 128;
#pragma unroll
            for (int jp = 0; jp < 16; jp += 2) {
                ull w0, w1;
                asm("ld.shared.v2.u64 {%0, %1}, [%2];"
                    : "=l"(w0), "=l"(w1) : "r"(rb + jp * 8));
                accA0[jp]     = fma2u(dA0, w0, accA0[jp]);
                accA0[jp + 1] = fma2u(dA0, w1, accA0[jp + 1]);
                accB0[jp]     = fma2u(dB0, w0, accB0[jp]);
                accB0[jp + 1] = fma2u(dB0, w1, accB0[jp + 1]);
                accA1[jp]     = fma2u(dA1, w0, accA1[jp]);
                accA1[jp + 1] = fma2u(dA1, w1, accA1[jp + 1]);
                accB1[jp]     = fma2u(dB1, w0, accB1[jp]);
                accB1[jp + 1] = fma2u(dB1, w1, accB1[jp + 1]);
            }
        }

        // ==== silu -> fp16x2 h2 (64 u32 regs; acc regs die) ====
        uint32_t hA0h[16], hB0h[16], hA1h[16], hB1h[16];
#pragma unroll
        for (int jp = 0; jp < 16; jp++) {
            hA0h[jp] = f2_to_h2(silup(accA0[jp]));
            hB0h[jp] = f2_to_h2(silup(accB0[jp]));
            hA1h[jp] = f2_to_h2(silup(accA1[jp]));
            hB1h[jp] = f2_to_h2(silup(accB1[jp]));
        }

        // ==== layer 3 in jp-quarter passes (acc3 = 16 ull) ====
        ull s4A0 = packf2(0.0f, 0.0f), s4B0 = s4A0, s4A1 = s4A0, s4B1 = s4A0;
#pragma unroll
        for (int q3 = 0; q3 < 4; q3++) {
            ull a3A0[4], a3B0[4], a3A1[4], a3B1[4];
#pragma unroll
            for (int jp = 0; jp < 4; jp++) {
                ull bb = B3p[q3 * 4 + jp];
                a3A0[jp] = bb; a3B0[jp] = bb; a3A1[jp] = bb; a3B1[jp] = bb;
            }
#pragma unroll 4
            for (int k = 0; k < 16; k++) {
                float2 fA0 = h2_to_f2(hA0h[k]);
                float2 fB0 = h2_to_f2(hB0h[k]);
                float2 fA1 = h2_to_f2(hA1h[k]);
                float2 fB1 = h2_to_f2(hB1h[k]);
#pragma unroll
                for (int s = 0; s < 2; s++) {   // i = 2k + s
                    ull dA0 = dupf(s ? fA0.y : fA0.x);
                    ull dB0 = dupf(s ? fB0.y : fB0.x);
                    ull dA1 = dupf(s ? fA1.y : fA1.x);
                    ull dB1 = dupf(s ? fB1.y : fB1.x);
                    unsigned rb = w3base + (unsigned)(2 * k + s) * 128 + q3 * 32;
                    ull w0, w1, w2v, w3v;
                    asm("ld.shared.v2.u64 {%0, %1}, [%2];"
                        : "=l"(w0), "=l"(w1) : "r"(rb));
                    asm("ld.shared.v2.u64 {%0, %1}, [%2];"
                        : "=l"(w2v), "=l"(w3v) : "r"(rb + 16));
                    a3A0[0] = fma2u(dA0, w0, a3A0[0]);
                    a3A0[1] = fma2u(dA0, w1, a3A0[1]);
                    a3A0[2] = fma2u(dA0, w2v, a3A0[2]);
                    a3A0[3] = fma2u(dA0, w3v, a3A0[3]);
                    a3B0[0] = fma2u(dB0, w0, a3B0[0]);
                    a3B0[1] = fma2u(dB0, w1, a3B0[1]);
                    a3B0[2] = fma2u(dB0, w2v, a3B0[2]);
                    a3B0[3] = fma2u(dB0, w3v, a3B0[3]);
                    a3A1[0] = fma2u(dA1, w0, a3A1[0]);
                    a3A1[1] = fma2u(dA1, w1, a3A1[1]);
                    a3A1[2] = fma2u(dA1, w2v, a3A1[2]);
                    a3A1[3] = fma2u(dA1, w3v, a3A1[3]);
                    a3B1[0] = fma2u(dB1, w0, a3B1[0]);
                    a3B1[1] = fma2u(dB1, w1, a3B1[1]);
                    a3B1[2] = fma2u(dB1, w2v, a3B1[2]);
                    a3B1[3] = fma2u(dB1, w3v, a3B1[3]);
                }
            }
            // silu + W4 dot for this quarter
#pragma unroll
            for (int jp = 0; jp < 4; jp++) {
                ull w4 = W4p[q3 * 4 + jp];
                s4A0 = fma2u(silup(a3A0[jp]), w4, s4A0);
                s4B0 = fma2u(silup(a3B0[jp]), w4, s4B0);
                s4A1 = fma2u(silup(a3A1[jp]), w4, s4A1);
                s4B1 = fma2u(silup(a3B1[jp]), w4, s4B1);
            }
        }

        // ==== scores + gaussian + warp reduce, per t ====
        float xa, xb, ya, yb;
        unpackf2(s4A0, xa, xb); unpackf2(s4B0, ya, yb);
        float scoreA0 = xa + xb + b4v, scoreB0 = ya + yb + b4v;
        unpackf2(s4A1, xa, xb); unpackf2(s4B1, ya, yb);
        float scoreA1 = xa + xb + b4v, scoreB1 = ya + yb + b4v;

        {
            float dtA = tn0 - dnA, dtB = tn0 - dnB;
            float wA = (dtA >= 0.0f) ? ex2f(wc_l2 * dtA * dtA) : 0.0f;
            float wB = (dtB >= 0.0f) ? ex2f(wc_l2 * dtB * dtB) : 0.0f;
            float part = scoreA0 * wA + scoreB0 * wB;
#pragma unroll
            for (int off = 16; off > 0; off >>= 1)
                part += __shfl_xor_sync(0xffffffffu, part, off);
            if (lane == 0) part_out[tt0] = part;
        }
        if (tt1 < T) {
            float dtA = tn1 - dnA, dtB = tn1 - dnB;
            float wA = (dtA >= 0.0f) ? ex2f(wc_l2 * dtA * dtA) : 0.0f;
            float wB = (dtB >= 0.0f) ? ex2f(wc_l2 * dtB * dtB) : 0.0f;
            float part = scoreA1 * wA + scoreB1 * wB;
#pragma unroll
            for (int off = 16; off > 0; off >>= 1)
                part += __shfl_xor_sync(0xffffffffu, part, off);
            if (lane == 0) part_out[tt1] = part;
        }
    }
}

// ---------------------------------------------------------------------------
// Kernel 3: combine quarter partials (deterministic).
// ---------------------------------------------------------------------------
__global__ void combine_kernel(float* __restrict__ out, int T) {
    int i = blockIdx.x * blockDim.x + threadIdx.x;
    if (i >= T) return;
    float p0 = g_part[0 * T_MAX + i];
    float p1 = g_part[1 * T_MAX + i];
    float p2 = g_part[2 * T_MAX + i];
    float p3 = g_part[3 * T_MAX + i];
    out[i] = (p0 + p1) + (p2 + p3);
}

extern "C" void kernel_launch(void* const* d_in, const int* in_sizes, int n_in,
                              void* d_out, int out_size) {
    const float* t_abs  = (const float*)d_in[0];
    const float* dose_t = (const float*)d_in[1];
    const float* amts   = (const float*)d_in[2];
    const float* ss     = (const float*)d_in[3];
    const float* ii     = (const float*)d_in[4];
    const float* span_p = (const float*)d_in[5];
    const float* logsig = (const float*)d_in[6];
    const float* W1     = (const float*)d_in[7];
    const float* b1     = (const float*)d_in[8];
    const float* W2     = (const float*)d_in[9];
    const float* b2     = (const float*)d_in[10];
    const float* W3     = (const float*)d_in[11];
    const float* b3     = (const float*)d_in[12];
    const float* W4     = (const float*)d_in[13];
    const float* b4     = (const float*)d_in[14];
    float* out = (float*)d_out;
    const int T = in_sizes[0];
    const int D = in_sizes[1];

    cudaFuncSetAttribute(dose_encoder_kernel,
                         cudaFuncAttributeMaxDynamicSharedMemorySize, SMEM_DYN);

    dtlast_kernel<<<(T + 255) / 256, 256>>>(t_abs, dose_t, span_p, T, D);

    dim3 grid((T + 63) / 64, 4);
    dose_encoder_kernel<<<grid, TPB, SMEM_DYN>>>(
        t_abs, dose_t, amts, ss, ii, span_p, logsig,
        W1, b1, W2, b2, W3, b3, W4, b4, T);

    combine_kernel<<<(T + 255) / 256, 256>>>(out, T);
}

// round 17
// speedup vs baseline: 1.1333x; 1.1333x over previous
#include <cuda_runtime.h>
#include <cstdint>

// ---------------------------------------------------------------------------
// DoseEncoder — R8 structure (best: 728us) + prescale-by-0.5 silu.
// Resubmission of R15 (container infra failure, kernel-side fault ruled out).
// Single delta vs the 728us kernel: 0.5 folded into W1t/W1dl/V/W2/b2/W3/b3
// so every pre-activation arrives as y = x/2 and silu(x) = y + y*tanh(y)
// (one fma2, no mul2). Everything else identical to R8.
//
//  * 3-kernel pipeline: dtlast (binary search) -> main -> combine.
//  * main: grid (T/64, 4). Block = 128 thr; warp w owns 16 t over the
//    block's 64 doses (2/thread, f32x2 lanes = hidden-j pairs).
//    NO barriers in the main loop; warps drift freely.
// ---------------------------------------------------------------------------

#define TPB   128
#define G_T   16          // t per warp
#define T_MAX 32768

typedef unsigned long long ull;

__device__ float g_dtlast[T_MAX];
__device__ float g_part[4 * T_MAX];

struct __align__(16) Smem {
    float4 V4[16][32];    // [jp][lane] = 0.5*{vA_2jp, vA_2jp+1, vB_2jp, vB_2jp+1}
    float  W2s[32 * 32];  // row-major [i][j], prescaled 0.5   (4 KB)
    float  W3s[32 * 32];  // prescaled 0.5                     (4 KB)
    float2 B2p[16];       // 0.5*b2 packed
    float2 B3p[16];       // 0.5*b3 packed
    float2 W4p[16];       // w4 packed (UNscaled)
    float2 W1tp[16];      // 0.5*{W1[0][2j], W1[0][2j+1]}
    float2 W1dlp[16];     // 0.5*{W1[2][2j], W1[2][2j+1]}
};

// ---- packed f32x2 helpers --------------------------------------------------
__device__ __forceinline__ ull packf2(float a, float b) {
    ull r; asm("mov.b64 %0, {%1, %2};" : "=l"(r) : "f"(a), "f"(b)); return r;
}
__device__ __forceinline__ void unpackf2(ull x, float& a, float& b) {
    asm("mov.b64 {%0, %1}, %2;" : "=f"(a), "=f"(b) : "l"(x));
}
__device__ __forceinline__ ull dupf(float a) {
    ull r; asm("mov.b64 %0, {%1, %1};" : "=l"(r) : "f"(a)); return r;
}
__device__ __forceinline__ ull fma2u(ull a, ull b, ull c) {
    ull r; asm("fma.rn.f32x2 %0, %1, %2, %3;" : "=l"(r) : "l"(a), "l"(b), "l"(c));
    return r;
}
__device__ __forceinline__ float ex2f(float x) {
    float r; asm("ex2.approx.f32 %0, %1;" : "=f"(r) : "f"(x)); return r;
}
__device__ __forceinline__ float tanhf_(float x) {
    float r; asm("tanh.approx.f32 %0, %1;" : "=f"(r) : "f"(x)); return r;
}
// input y = x/2 (prescaled). silu(x) = y + y*tanh(y), both packed lanes.
__device__ __forceinline__ ull silup(ull y) {
    float y0, y1; unpackf2(y, y0, y1);
    float t0 = tanhf_(y0), t1 = tanhf_(y1);
    return fma2u(y, packf2(t0, t1), y);
}

// One 32->32 layer + SiLU for two doses. Weights (prescaled) row-major in smem.
__device__ __forceinline__ void mlp_layer(unsigned wbase,
                                          const float2* __restrict__ Bp,
                                          const ull* __restrict__ hA,
                                          const ull* __restrict__ hB,
                                          ull* __restrict__ oA,
                                          ull* __restrict__ oB) {
    ull accA[16], accB[16];
#pragma unroll
    for (int jp = 0; jp < 16; jp++) {
        float2 b = Bp[jp];
        ull bb = packf2(b.x, b.y);
        accA[jp] = bb; accB[jp] = bb;
    }
#pragma unroll
    for (int k = 0; k < 16; k++) {
        float a0, a1, b0, b1;
        unpackf2(hA[k], a0, a1);
        unpackf2(hB[k], b0, b1);
        {
            ull dA = dupf(a0), dB = dupf(b0);
            unsigned rb = wbase + (2 * k) * 128;
#pragma unroll
            for (int jp = 0; jp < 16; jp += 2) {
                ull w0, w1;
                asm("ld.shared.v2.u64 {%0, %1}, [%2];"
                    : "=l"(w0), "=l"(w1) : "r"(rb + jp * 8));
                accA[jp]     = fma2u(dA, w0, accA[jp]);
                accA[jp + 1] = fma2u(dA, w1, accA[jp + 1]);
                accB[jp]     = fma2u(dB, w0, accB[jp]);
                accB[jp + 1] = fma2u(dB, w1, accB[jp + 1]);
            }
        }
        {
            ull dA = dupf(a1), dB = dupf(b1);
            unsigned rb = wbase + (2 * k + 1) * 128;
#pragma unroll
            for (int jp = 0; jp < 16; jp += 2) {
                ull w0, w1;
                asm("ld.shared.v2.u64 {%0, %1}, [%2];"
                    : "=l"(w0), "=l"(w1) : "r"(rb + jp * 8));
                accA[jp]     = fma2u(dA, w0, accA[jp]);
                accA[jp + 1] = fma2u(dA, w1, accA[jp + 1]);
                accB[jp]     = fma2u(dB, w0, accB[jp]);
                accB[jp + 1] = fma2u(dB, w1, accB[jp + 1]);
            }
        }
    }
#pragma unroll
    for (int jp = 0; jp < 16; jp++) {
        oA[jp] = silup(accA[jp]);
        oB[jp] = silup(accB[jp]);
    }
}

// ---------------------------------------------------------------------------
// Kernel 1: dt_last via binary search (doses sorted ascending).
// ---------------------------------------------------------------------------
__global__ void dtlast_kernel(const float* __restrict__ t_abs,
                              const float* __restrict__ dose_t,
                              const float* __restrict__ span_p,
                              int T, int D) {
    int i = blockIdx.x * blockDim.x + threadIdx.x;
    if (i >= T) return;
    float ta = t_abs[i];
    float inv_span = 1.0f / span_p[0];
    int pos = 0;
#pragma unroll
    for (int s = 256; s > 0; s >>= 1) {
        int np = pos + s;
        if (np <= D && dose_t[np - 1] <= ta) pos = np;
    }
    g_dtlast[i] = (pos > 0) ? (ta - dose_t[pos - 1]) * inv_span
                            : __int_as_float(0x7f800000);
}

// ---------------------------------------------------------------------------
// Kernel 2: main. grid = (ceil(T/64), 4). Block = 64 t x 64 doses.
// ---------------------------------------------------------------------------
__global__ void __launch_bounds__(TPB, 3)
dose_encoder_kernel(const float* __restrict__ t_abs,
                    const float* __restrict__ dose_t,
                    const float* __restrict__ amts,
                    const float* __restrict__ ss,
                    const float* __restrict__ ii,
                    const float* __restrict__ span_p,
                    const float* __restrict__ logsig,
                    const float* __restrict__ W1,
                    const float* __restrict__ b1,
                    const float* __restrict__ W2,
                    const float* __restrict__ b2,
                    const float* __restrict__ W3,
                    const float* __restrict__ b3,
                    const float* __restrict__ W4,
                    const float* __restrict__ b4,
                    int T) {
    __shared__ Smem S;
    const int tid  = threadIdx.x;
    const int lane = tid & 31;
    const int warp = tid >> 5;
    const int q    = blockIdx.y;           // dose quarter
    const int dq0  = q * 64;

    const float span     = span_p[0];
    const float inv_span = 1.0f / span;
    const float sigma    = expf(logsig[0]);
    const float wc_l2    = -0.5f / (sigma * sigma) * 1.4426950408889634f;

    // ---- prolog: stage prescaled weights ----
    for (int idx = tid; idx < 1024; idx += TPB) {
        S.W2s[idx] = 0.5f * W2[idx];
        S.W3s[idx] = 0.5f * W3[idx];
    }
    if (tid < 16) {
        S.B2p[tid]   = make_float2(0.5f * b2[2 * tid], 0.5f * b2[2 * tid + 1]);
        S.B3p[tid]   = make_float2(0.5f * b3[2 * tid], 0.5f * b3[2 * tid + 1]);
        S.W4p[tid]   = make_float2(W4[2 * tid], W4[2 * tid + 1]);
        S.W1tp[tid]  = make_float2(0.5f * W1[2 * tid], 0.5f * W1[2 * tid + 1]);
        S.W1dlp[tid] = make_float2(0.5f * W1[64 + 2 * tid], 0.5f * W1[64 + 2 * tid + 1]);
    }

    // ---- V vectors for this block's 64 doses (prescaled 0.5, incl. b1) ----
    {
        int l  = tid & 31;
        int jb = (tid >> 5) * 4;
        int d0 = dq0 + 2 * l, d1 = d0 + 1;
        float dn0 = dose_t[d0] * inv_span;
        float dn1 = dose_t[d1] * inv_span;
        float la0 = log1pf(amts[d0]), la1 = log1pf(amts[d1]);
        float spe = 1.0f / (span + 1e-6f);
        float ssn0 = ss[d0] * spe, ssn1 = ss[d1] * spe;
        float iin0 = ii[d0] * spe, iin1 = ii[d1] * spe;
        for (int jp = jb; jp < jb + 4; jp++) {
            int j0 = 2 * jp, j1 = j0 + 1;
            float w_dt0 = W1[j0],       w_dt1 = W1[j1];
            float w_la0 = W1[32 + j0],  w_la1 = W1[32 + j1];
            float w_ss0 = W1[96 + j0],  w_ss1 = W1[96 + j1];
            float w_ii0 = W1[128 + j0], w_ii1 = W1[128 + j1];
            float bb0 = b1[j0], bb1 = b1[j1];
            float4 o;
            o.x = 0.5f * fmaf(-dn0, w_dt0, fmaf(la0, w_la0, fmaf(ssn0, w_ss0, fmaf(iin0, w_ii0, bb0))));
            o.y = 0.5f * fmaf(-dn0, w_dt1, fmaf(la0, w_la1, fmaf(ssn0, w_ss1, fmaf(iin0, w_ii1, bb1))));
            o.z = 0.5f * fmaf(-dn1, w_dt0, fmaf(la1, w_la0, fmaf(ssn1, w_ss0, fmaf(iin1, w_ii0, bb0))));
            o.w = 0.5f * fmaf(-dn1, w_dt1, fmaf(la1, w_la1, fmaf(ssn1, w_ss1, fmaf(iin1, w_ii1, bb1))));
            S.V4[jp][l] = o;
        }
    }
    __syncthreads();   // the ONLY block barrier

    // per-thread dose constants
    const int d0 = dq0 + 2 * lane, d1 = d0 + 1;
    const float dn0 = dose_t[d0] * inv_span;
    const float dn1 = dose_t[d1] * inv_span;
    const float b4v = b4[0];
    const unsigned w2base = (unsigned)__cvta_generic_to_shared(S.W2s);
    const unsigned w3base = (unsigned)__cvta_generic_to_shared(S.W3s);

    const int tbase = blockIdx.x * (4 * G_T) + warp * G_T;
    float* __restrict__ part_out = g_part + q * T_MAX;

#pragma unroll 1
    for (int g = 0; g < G_T; g++) {
        int tt = tbase + g;
        if (tt >= T) break;
        float tnorm = t_abs[tt] * inv_span;
        float dl    = g_dtlast[tt];
        ull tn2 = dupf(tnorm);
        ull dl2 = dupf(dl);

        // ---- layer 1: pre/2 = tn*(W1t/2) + dl*(W1dl/2) + V/2, then silu ----
        ull hA[16], hB[16], h2A[16], h2B[16];
#pragma unroll
        for (int jp = 0; jp < 16; jp++) {
            float4 v  = S.V4[jp][lane];
            float2 wt = S.W1tp[jp];
            float2 wd = S.W1dlp[jp];
            ull wtp = packf2(wt.x, wt.y);
            ull wdp = packf2(wd.x, wd.y);
            ull u   = fma2u(tn2, wtp, fma2u(dl2, wdp, packf2(v.x, v.y)));
            ull ub  = fma2u(tn2, wtp, fma2u(dl2, wdp, packf2(v.z, v.w)));
            hA[jp] = silup(u);
            hB[jp] = silup(ub);
        }

        // ---- layers 2, 3 ----
        mlp_layer(w2base, S.B2p, hA, hB, h2A, h2B);
        mlp_layer(w3base, S.B3p, h2A, h2B, hA, hB);

        // ---- layer 4 ----
        ull sA = packf2(0.0f, 0.0f), sB = sA;
#pragma unroll
        for (int jp = 0; jp < 16; jp++) {
            float2 w4 = S.W4p[jp];
            ull wp = packf2(w4.x, w4.y);
            sA = fma2u(hA[jp], wp, sA);
            sB = fma2u(hB[jp], wp, sB);
        }
        float sa0, sa1, sb0, sb1;
        unpackf2(sA, sa0, sa1);
        unpackf2(sB, sb0, sb1);
        float scoreA = sa0 + sa1 + b4v;
        float scoreB = sb0 + sb1 + b4v;

        // ---- gaussian weight + masked accumulate over this warp's 64 doses ----
        float dtA = tnorm - dn0;
        float dtB = tnorm - dn1;
        float wA = (dtA >= 0.0f) ? ex2f(wc_l2 * dtA * dtA) : 0.0f;
        float wB = (dtB >= 0.0f) ? ex2f(wc_l2 * dtB * dtB) : 0.0f;
        float part = scoreA * wA + scoreB * wB;
#pragma unroll
        for (int off = 16; off > 0; off >>= 1)
            part += __shfl_xor_sync(0xffffffffu, part, off);
        if (lane == 0) part_out[tt] = part;
    }
}

// ---------------------------------------------------------------------------
// Kernel 3: combine quarter partials (deterministic).
// ---------------------------------------------------------------------------
__global__ void combine_kernel(float* __restrict__ out, int T) {
    int i = blockIdx.x * blockDim.x + threadIdx.x;
    if (i >= T) return;
    float p0 = g_part[0 * T_MAX + i];
    float p1 = g_part[1 * T_MAX + i];
    float p2 = g_part[2 * T_MAX + i];
    float p3 = g_part[3 * T_MAX + i];
    out[i] = (p0 + p1) + (p2 + p3);
}

extern "C" void kernel_launch(void* const* d_in, const int* in_sizes, int n_in,
                              void* d_out, int out_size) {
    const float* t_abs  = (const float*)d_in[0];
    const float* dose_t = (const float*)d_in[1];
    const float* amts   = (const float*)d_in[2];
    const float* ss     = (const float*)d_in[3];
    const float* ii     = (const float*)d_in[4];
    const float* span_p = (const float*)d_in[5];
    const float* logsig = (const float*)d_in[6];
    const float* W1     = (const float*)d_in[7];
    const float* b1     = (const float*)d_in[8];
    const float* W2     = (const float*)d_in[9];
    const float* b2     = (const float*)d_in[10];
    const float* W3     = (const float*)d_in[11];
    const float* b3     = (const float*)d_in[12];
    const float* W4     = (const float*)d_in[13];
    const float* b4     = (const float*)d_in[14];
    float* out = (float*)d_out;
    const int T = in_sizes[0];
    const int D = in_sizes[1];

    dtlast_kernel<<<(T + 255) / 256, 256>>>(t_abs, dose_t, span_p, T, D);

    dim3 grid((T + 4 * G_T - 1) / (4 * G_T), 4);
    dose_encoder_kernel<<<grid, TPB>>>(
        t_abs, dose_t, amts, ss, ii, span_p, logsig,
        W1, b1, W2, b2, W3, b3, W4, b4, T);

    combine_kernel<<<(T + 255) / 256, 256>>>(out, T);
}